// round 11
// baseline (speedup 1.0000x reference)
#include <cuda_runtime.h>
#include <cuda_fp16.h>
#include <cstdint>

// ============================================================================
// StagePolicyNetwork: gather -> [208x128] GEMM -> relu -> [128x64] GEMM
// -> relu -> [64x1] dot.  fp16 m16n8k16 mma.sync (fp32 accum).
// 256 threads, 8 warps, warp tile 32x64 (halves A-fragment LDS redundancy),
// ldmatrix.x4 A loads. Persistent CTAs, 128-row tiles. compute_103-safe.
// ============================================================================

__device__ __forceinline__ uint32_t smem_u32(const void* p) {
    uint32_t a;
    asm("{ .reg .u64 t; cvta.to.shared.u64 t, %1; cvt.u32.u64 %0, t; }" : "=r"(a) : "l"(p));
    return a;
}
__device__ __forceinline__ uint32_t pack_h2(float a, float b) {
    __half2 h = __floats2half2_rn(a, b);
    return *reinterpret_cast<uint32_t*>(&h);
}
__device__ __forceinline__ void ldmx4(uint32_t& r0, uint32_t& r1, uint32_t& r2, uint32_t& r3,
                                      uint32_t addr) {
    asm volatile("ldmatrix.sync.aligned.m8n8.x4.shared.b16 {%0,%1,%2,%3}, [%4];"
                 : "=r"(r0), "=r"(r1), "=r"(r2), "=r"(r3) : "r"(addr));
}
__device__ __forceinline__ void mma_f16(float& c0, float& c1, float& c2, float& c3,
                                        uint32_t a0, uint32_t a1, uint32_t a2, uint32_t a3,
                                        uint32_t b0, uint32_t b1) {
    asm volatile(
        "mma.sync.aligned.m16n8k16.row.col.f32.f16.f16.f32 "
        "{%0,%1,%2,%3}, {%4,%5,%6,%7}, {%8,%9}, {%0,%1,%2,%3};"
        : "+f"(c0), "+f"(c1), "+f"(c2), "+f"(c3)
        : "r"(a0), "r"(a1), "r"(a2), "r"(a3), "r"(b0), "r"(b1));
}

// ---------------- constants --------------------------------------------------
static constexpr int TILE = 128;
static constexpr int KS1 = 13;          // 208/16 k-steps, layer 1
static constexpr int KS2 = 8;           // 128/16 k-steps, layer 2
static constexpr int RSTRIDE = 48;      // bytes per row (32B data + 16B pad)
static constexpr int SSTRIDE = 128 * RSTRIDE;   // 6144 per k-step

// SMEM layout (bytes)
static constexpr int SM_W1F  = 0;                      // 13*16*32*8 = 53248
static constexpr int SM_W2F  = 53248;                  // 8*8*32*8   = 16384
static constexpr int SM_A    = 69632;                  // 13*6144    = 79872
static constexpr int SM_H    = 149504;                 // 8*6144     = 49152
static constexpr int SM_B1   = 198656;                 // 512
static constexpr int SM_B2   = 199168;                 // 256
static constexpr int SM_W3   = 199424;                 // 256
static constexpr int SM_PART = 199680;                 // 128*2*4 = 1024
static constexpr int SM_CUM  = 200704;                 // 80
static constexpr int SMEM_TOTAL = 200832;

__global__ __launch_bounds__(256, 1)
void stage_policy_kernel(
    const float* __restrict__ x, const float* __restrict__ hn,
    const float* __restrict__ hd, const float* __restrict__ hg,
    const float* __restrict__ W1g, const float* __restrict__ b1g,
    const float* __restrict__ W2g, const float* __restrict__ b2g,
    const float* __restrict__ W3g, const float* __restrict__ b3g,
    const int* __restrict__ stage_idx, const int* __restrict__ batch,
    const int* __restrict__ nsa,
    float* __restrict__ out, int M, int G, int ntiles)
{
    extern __shared__ char smem[];
    const uint32_t sba = smem_u32(smem) + SM_A;
    const uint32_t sbh = smem_u32(smem) + SM_H;
    const int tid  = threadIdx.x;
    const int lane = tid & 31;
    const int g4   = lane >> 2;     // row within 8
    const int t4   = lane & 3;      // k/col pair
    const int wid  = tid >> 5;
    const int mg   = wid >> 1;      // rows 32*mg .. +32
    const int ng   = wid & 1;       // L1 cols 64*ng, L2 cols 32*ng

    float* sB1  = (float*)(smem + SM_B1);
    float* sB2  = (float*)(smem + SM_B2);
    float* sW3  = (float*)(smem + SM_W3);
    float* sPt  = (float*)(smem + SM_PART);
    int*   sCum = (int*)(smem + SM_CUM);

    // ldmatrix per-lane offset within a 16x16 fragment (row-major, RSTRIDE)
    const uint32_t laneoff = (uint32_t)(((lane & 7) + 8 * ((lane >> 3) & 1)) * RSTRIDE
                                        + (lane >> 4) * 16);

    // ---------------- one-time fills ----------------
    // W1 fragment-major fp16: [s(13)][nblk(16)][lane(32)] x {b0,b1}
    for (int i = tid; i < KS1 * 16 * 32; i += 256) {
        const int l = i & 31, n = (i >> 5) & 15, s = i >> 9;
        const int k0 = 16 * s + 2 * (l & 3);
        const int col = 8 * n + (l >> 2);
        uint2 v;
        v.x = pack_h2(W1g[k0 * 128 + col],       W1g[(k0 + 1) * 128 + col]);
        v.y = pack_h2(W1g[(k0 + 8) * 128 + col], W1g[(k0 + 9) * 128 + col]);
        ((uint2*)(smem + SM_W1F))[i] = v;
    }
    // W2 fragment-major fp16: [s(8)][nblk(8)][lane(32)] x {b0,b1}
    for (int i = tid; i < KS2 * 8 * 32; i += 256) {
        const int l = i & 31, n = (i >> 5) & 7, s = i >> 8;
        const int k0 = 16 * s + 2 * (l & 3);
        const int col = 8 * n + (l >> 2);
        uint2 v;
        v.x = pack_h2(W2g[k0 * 64 + col],       W2g[(k0 + 1) * 64 + col]);
        v.y = pack_h2(W2g[(k0 + 8) * 64 + col], W2g[(k0 + 9) * 64 + col]);
        ((uint2*)(smem + SM_W2F))[i] = v;
    }
    if (tid < 128) sB1[tid] = b1g[tid];
    if (tid >= 128 && tid < 192) sB2[tid - 128] = b2g[tid - 128];
    if (tid >= 192 && tid < 256) sW3[tid - 192] = W3g[tid - 192];
    if (tid == 0) {
        int c = 0; sCum[0] = 0;
        for (int i = 0; i < G; i++) { c += nsa[i]; sCum[i + 1] = c; }
    }
    const float b3v = b3g[0];
    __syncthreads();

    // gather role: 2 threads per row; each covers 8 cols (16B fp16) per k-step
    const int grow = tid >> 1;      // 0..127
    const int gh   = tid & 1;       // k half within step

    // carried per-tile gather state (prefetched one tile ahead)
    int cidx, cbd, cgg;
    {
        const int gr0 = blockIdx.x * TILE + grow;
        const int grc = (gr0 < M) ? gr0 : (M - 1);
        cidx = stage_idx[grc];
        cbd  = batch[cidx];
        int g = 0;
        #pragma unroll 1
        while (g + 1 < G && grc >= sCum[g + 1]) g++;
        cgg = g;
    }

    for (int tile = blockIdx.x; tile < ntiles; tile += gridDim.x) {
        const float* px  = x  + (size_t)cidx * 16;
        const float* phn = hn + (size_t)cidx * 64;
        const float* phd = hd + (size_t)cbd  * 64;
        const float* phg = hg + (size_t)cgg  * 64;

        // ---- gather: per k-step 2x LDG.128 -> fp16 -> STS.128 into SM_A ----
        char* arow = smem + SM_A + grow * RSTRIDE + gh * 16;
        #pragma unroll
        for (int j = 0; j < KS1; j++) {
            const int col = 16 * j + 8 * gh;
            const float* p;
            if      (col < 16)  p = px  + col;
            else if (col < 80)  p = phn + (col - 16);
            else if (col < 144) p = phd + (col - 80);
            else                p = phg + (col - 144);
            const float4 v0 = *(const float4*)p;
            const float4 v1 = *(const float4*)(p + 4);
            uint4 h;
            h.x = pack_h2(v0.x, v0.y);
            h.y = pack_h2(v0.z, v0.w);
            h.z = pack_h2(v1.x, v1.y);
            h.w = pack_h2(v1.z, v1.w);
            *(uint4*)(arow + j * SSTRIDE) = h;
        }

        // prefetch next tile's indices (hidden under MMA phase)
        int nidx, nbd, ngg;
        {
            const int tn  = tile + gridDim.x;
            const int g0  = tn * TILE + grow;
            const int grn = (tn < ntiles) ? ((g0 < M) ? g0 : (M - 1)) : 0;
            nidx = stage_idx[grn];
            nbd  = batch[nidx];
            int g = 0;
            #pragma unroll 1
            while (g + 1 < G && grn >= sCum[g + 1]) g++;
            ngg = g;
        }
        __syncthreads();   // bar 1: A ready

        // ---------------- layer 1: 13 k-steps, warp tile 32x64 ----------------
        float acc[2][8][4];
        #pragma unroll
        for (int a = 0; a < 2; a++)
            #pragma unroll
            for (int b = 0; b < 8; b++)
                #pragma unroll
                for (int w = 0; w < 4; w++) acc[a][b][w] = 0.f;

        const uint32_t abase = sba + (uint32_t)(32 * mg) * RSTRIDE + laneoff;
        #pragma unroll
        for (int s = 0; s < KS1; s++) {
            uint32_t a[2][4];
            ldmx4(a[0][0], a[0][1], a[0][2], a[0][3], abase + s * SSTRIDE);
            ldmx4(a[1][0], a[1][1], a[1][2], a[1][3], abase + s * SSTRIDE + 16 * RSTRIDE);
            uint2 bf[8];
            #pragma unroll
            for (int nl = 0; nl < 8; nl++)
                bf[nl] = ((const uint2*)(smem + SM_W1F))[(s * 16 + 8 * ng + nl) * 32 + lane];
            #pragma unroll
            for (int ml = 0; ml < 2; ml++)
                #pragma unroll
                for (int nl = 0; nl < 8; nl++)
                    mma_f16(acc[ml][nl][0], acc[ml][nl][1], acc[ml][nl][2], acc[ml][nl][3],
                            a[ml][0], a[ml][1], a[ml][2], a[ml][3],
                            bf[nl].x, bf[nl].y);
        }

        // ---- epilogue 1: +b1, relu, fp16 -> SM_H ----
        #pragma unroll
        for (int ml = 0; ml < 2; ml++) {
            #pragma unroll
            for (int nl = 0; nl < 8; nl++) {
                const int col0 = 64 * ng + 8 * nl + 2 * t4;
                const float2 bb = *(const float2*)(sB1 + col0);
                const uint32_t lo = pack_h2(fmaxf(acc[ml][nl][0] + bb.x, 0.f),
                                            fmaxf(acc[ml][nl][1] + bb.y, 0.f));
                const uint32_t hi = pack_h2(fmaxf(acc[ml][nl][2] + bb.x, 0.f),
                                            fmaxf(acc[ml][nl][3] + bb.y, 0.f));
                const int s2  = col0 >> 4;
                const int kin = col0 & 15;
                const int r0  = 32 * mg + 16 * ml + g4;
                char* hp = smem + SM_H + s2 * SSTRIDE + r0 * RSTRIDE + kin * 2;
                *(uint32_t*)(hp)               = lo;   // row r0
                *(uint32_t*)(hp + 8 * RSTRIDE) = hi;   // row r0+8
            }
        }
        __syncthreads();   // bar 2: H ready

        // ---------------- layer 2: 8 k-steps, warp tile 32x32 ----------------
        float ac2[2][4][4];
        #pragma unroll
        for (int a = 0; a < 2; a++)
            #pragma unroll
            for (int b = 0; b < 4; b++)
                #pragma unroll
                for (int w = 0; w < 4; w++) ac2[a][b][w] = 0.f;

        const uint32_t hbase = sbh + (uint32_t)(32 * mg) * RSTRIDE + laneoff;
        #pragma unroll
        for (int s = 0; s < KS2; s++) {
            uint32_t a[2][4];
            ldmx4(a[0][0], a[0][1], a[0][2], a[0][3], hbase + s * SSTRIDE);
            ldmx4(a[1][0], a[1][1], a[1][2], a[1][3], hbase + s * SSTRIDE + 16 * RSTRIDE);
            uint2 bf[4];
            #pragma unroll
            for (int nl = 0; nl < 4; nl++)
                bf[nl] = ((const uint2*)(smem + SM_W2F))[(s * 8 + 4 * ng + nl) * 32 + lane];
            #pragma unroll
            for (int ml = 0; ml < 2; ml++)
                #pragma unroll
                for (int nl = 0; nl < 4; nl++)
                    mma_f16(ac2[ml][nl][0], ac2[ml][nl][1], ac2[ml][nl][2], ac2[ml][nl][3],
                            a[ml][0], a[ml][1], a[ml][2], a[ml][3],
                            bf[nl].x, bf[nl].y);
        }

        // ---- epilogue 2: +b2, relu, dot W3, reduce ----
        #pragma unroll
        for (int ml = 0; ml < 2; ml++) {
            float p0 = 0.f, p1 = 0.f;
            #pragma unroll
            for (int nl = 0; nl < 4; nl++) {
                const int col0 = 32 * ng + 8 * nl + 2 * t4;
                const float2 bb = *(const float2*)(sB2 + col0);
                const float2 ww = *(const float2*)(sW3 + col0);
                p0 += fmaxf(ac2[ml][nl][0] + bb.x, 0.f) * ww.x
                    + fmaxf(ac2[ml][nl][1] + bb.y, 0.f) * ww.y;
                p1 += fmaxf(ac2[ml][nl][2] + bb.x, 0.f) * ww.x
                    + fmaxf(ac2[ml][nl][3] + bb.y, 0.f) * ww.y;
            }
            p0 += __shfl_xor_sync(0xffffffffu, p0, 1);
            p0 += __shfl_xor_sync(0xffffffffu, p0, 2);
            p1 += __shfl_xor_sync(0xffffffffu, p1, 1);
            p1 += __shfl_xor_sync(0xffffffffu, p1, 2);
            if (t4 == 0) {
                const int r0 = 32 * mg + 16 * ml + g4;
                sPt[r0 * 2 + ng]       = p0;
                sPt[(r0 + 8) * 2 + ng] = p1;
            }
        }
        __syncthreads();   // bar 3: partials ready

        if (tid < 128) {
            const float2 p = ((const float2*)sPt)[tid];
            const int go = tile * TILE + tid;
            if (go < M) out[go] = p.x + p.y + b3v;
        }

        cidx = nidx; cbd = nbd; cgg = ngg;
    }
}

// ---------------------------------------------------------------------------
extern "C" void kernel_launch(void* const* d_in, const int* in_sizes, int n_in,
                              void* d_out, int out_size) {
    const float* x   = (const float*)d_in[0];
    const float* hn  = (const float*)d_in[1];
    const float* hd  = (const float*)d_in[2];
    const float* hg  = (const float*)d_in[3];
    const float* W1  = (const float*)d_in[4];
    const float* b1  = (const float*)d_in[5];
    const float* W2  = (const float*)d_in[6];
    const float* b2  = (const float*)d_in[7];
    const float* W3  = (const float*)d_in[8];
    const float* b3  = (const float*)d_in[9];
    const int* sidx  = (const int*)d_in[10];
    const int* batch = (const int*)d_in[11];
    const int* nsa   = (const int*)d_in[12];
    float* out = (float*)d_out;

    const int M = in_sizes[10];
    const int G = in_sizes[12];
    const int ntiles = (M + TILE - 1) / TILE;

    static int sms = 0;
    if (sms == 0) {
        cudaDeviceGetAttribute(&sms, cudaDevAttrMultiProcessorCount, 0);
        cudaFuncSetAttribute(stage_policy_kernel,
                             cudaFuncAttributeMaxDynamicSharedMemorySize, SMEM_TOTAL);
        if (sms <= 0) sms = 148;
    }
    const int grid = (ntiles < sms) ? ntiles : sms;

    stage_policy_kernel<<<grid, 256, SMEM_TOTAL>>>(
        x, hn, hd, hg, W1, b1, W2, b2, W3, b3, sidx, batch, nsa, out, M, G, ntiles);
}

// round 13
// speedup vs baseline: 1.2552x; 1.2552x over previous
#include <cuda_runtime.h>
#include <cuda_fp16.h>
#include <cstdint>

// ============================================================================
// StagePolicyNetwork with algebraic K-reduction:
//   PD[d] = h_dag[d] @ W1[80:144]   (precomputed, fp32, Dx128)
//   PG[g] = b1 + h_glob[g] @ W1[144:208]  (precomputed, Gx128)
//   main: gather(x,hn) -> [80x128] fp16 GEMM -> +PD[bd]+PG[g], relu
//         -> [128x64] fp16 GEMM -> relu -> [64x1] dot.
// Persistent CTAs, 512 threads, 128-row tiles, m16n8k16 fp32-accum.
// compute_103-safe (no tcgen05).
// ============================================================================

__device__ float g_PD[8192 * 128];   // h_dag @ W1[80:144]
__device__ float g_PG[128 * 128];    // b1 + h_glob @ W1[144:208]

__device__ __forceinline__ uint32_t pack_h2(float a, float b) {
    __half2 h = __floats2half2_rn(a, b);
    return *reinterpret_cast<uint32_t*>(&h);
}
__device__ __forceinline__ void mma_f16(float& c0, float& c1, float& c2, float& c3,
                                        uint32_t a0, uint32_t a1, uint32_t a2, uint32_t a3,
                                        uint32_t b0, uint32_t b1) {
    asm volatile(
        "mma.sync.aligned.m16n8k16.row.col.f32.f16.f16.f32 "
        "{%0,%1,%2,%3}, {%4,%5,%6,%7}, {%8,%9}, {%0,%1,%2,%3};"
        : "+f"(c0), "+f"(c1), "+f"(c2), "+f"(c3)
        : "r"(a0), "r"(a1), "r"(a2), "r"(a3), "r"(b0), "r"(b1));
}

// ---------------- constants --------------------------------------------------
static constexpr int TILE = 128;
static constexpr int NS1 = 5;           // 80/16 k-steps, layer 1 (x + h_node)
static constexpr int KS2 = 8;           // 128/16 k-steps, layer 2
static constexpr int RSTRIDE = 48;      // bytes per A/H row (32B data + 16B pad)
static constexpr int SSTRIDE = 128 * RSTRIDE;   // 6144 per k-step

// SMEM layout (bytes)
static constexpr int SM_W1F  = 0;        // 5*16*32*8  = 20480
static constexpr int SM_W2F  = 20480;    // 8*8*32*8   = 16384
static constexpr int SM_A    = 36864;    // 5*6144     = 30720
static constexpr int SM_H    = 67584;    // 8*6144     = 49152
static constexpr int SM_B2   = 116736;   // 256
static constexpr int SM_W3   = 116992;   // 256
static constexpr int SM_PART = 117248;   // 128*4*4 = 2048
static constexpr int SM_CUM  = 119296;   // 128
static constexpr int SM_BD   = 119424;   // 512 (per-row dag id)
static constexpr int SM_G    = 119936;   // 512 (per-row glob id)
static constexpr int SMEM_TOTAL = 120448;

// ---------------- precompute kernel ------------------------------------------
__global__ void precompute_pdg(const float* __restrict__ hd,
                               const float* __restrict__ hg,
                               const float* __restrict__ W1g,
                               const float* __restrict__ b1g,
                               int D, int G)
{
    const int c = threadIdx.x;           // 0..127
    const int r = blockIdx.x;
    if (r < D) {
        const float* v = hd + (size_t)r * 64;
        float s = 0.f;
        #pragma unroll 8
        for (int j = 0; j < 64; j++) s = fmaf(v[j], W1g[(80 + j) * 128 + c], s);
        g_PD[r * 128 + c] = s;
    } else {
        const int g = r - D;
        const float* v = hg + (size_t)g * 64;
        float s = b1g[c];
        #pragma unroll 8
        for (int j = 0; j < 64; j++) s = fmaf(v[j], W1g[(144 + j) * 128 + c], s);
        g_PG[g * 128 + c] = s;
    }
}

// ---------------- main kernel --------------------------------------------------
__global__ __launch_bounds__(512, 1)
void stage_policy_kernel(
    const float* __restrict__ x, const float* __restrict__ hn,
    const float* __restrict__ W1g,
    const float* __restrict__ W2g, const float* __restrict__ b2g,
    const float* __restrict__ W3g, const float* __restrict__ b3g,
    const int* __restrict__ stage_idx, const int* __restrict__ batch,
    const int* __restrict__ nsa,
    float* __restrict__ out, int M, int G, int ntiles)
{
    extern __shared__ char smem[];
    const int tid  = threadIdx.x;
    const int lane = tid & 31;
    const int g4   = lane >> 2;     // row within 8
    const int t4   = lane & 3;      // k/col pair
    const int wid  = tid >> 5;
    const int mg   = wid >> 2;      // rows 32*mg .. +32
    const int ng   = wid & 3;       // L1 cols 32*ng, L2 cols 16*ng

    float* sB2  = (float*)(smem + SM_B2);
    float* sW3  = (float*)(smem + SM_W3);
    float* sPt  = (float*)(smem + SM_PART);
    int*   sCum = (int*)(smem + SM_CUM);
    int*   sBD  = (int*)(smem + SM_BD);
    int*   sG   = (int*)(smem + SM_G);

    // ---------------- one-time fills ----------------
    // W1 fragment-major fp16 (k = 0..79 only): [s(5)][nblk(16)][lane(32)] x {b0,b1}
    for (int i = tid; i < NS1 * 16 * 32; i += 512) {
        const int l = i & 31, n = (i >> 5) & 15, s = i >> 9;
        const int k0 = 16 * s + 2 * (l & 3);
        const int col = 8 * n + (l >> 2);
        uint2 v;
        v.x = pack_h2(W1g[k0 * 128 + col],       W1g[(k0 + 1) * 128 + col]);
        v.y = pack_h2(W1g[(k0 + 8) * 128 + col], W1g[(k0 + 9) * 128 + col]);
        ((uint2*)(smem + SM_W1F))[i] = v;
    }
    // W2 fragment-major fp16: [s(8)][nblk(8)][lane(32)] x {b0,b1}
    for (int i = tid; i < KS2 * 8 * 32; i += 512) {
        const int l = i & 31, n = (i >> 5) & 7, s = i >> 8;
        const int k0 = 16 * s + 2 * (l & 3);
        const int col = 8 * n + (l >> 2);
        uint2 v;
        v.x = pack_h2(W2g[k0 * 64 + col],       W2g[(k0 + 1) * 64 + col]);
        v.y = pack_h2(W2g[(k0 + 8) * 64 + col], W2g[(k0 + 9) * 64 + col]);
        ((uint2*)(smem + SM_W2F))[i] = v;
    }
    if (tid >= 128 && tid < 192) sB2[tid - 128] = b2g[tid - 128];
    if (tid >= 192 && tid < 256) sW3[tid - 192] = W3g[tid - 192];
    if (tid == 0) {
        int c = 0; sCum[0] = 0;
        for (int i = 0; i < G; i++) { c += nsa[i]; sCum[i + 1] = c; }
    }
    const float b3v = b3g[0];
    __syncthreads();

    // gather role: 4 threads per row (grow in [0,128)); q = 4-col quarter
    const int grow = tid >> 2;      // 0..127
    const int q    = tid & 3;       // quarter within k-step (4 cols)

    // carried per-tile gather state (prefetched one tile ahead)
    int cidx, cbd, cgg;
    {
        const int gr0 = blockIdx.x * TILE + grow;
        const int grc = (gr0 < M) ? gr0 : (M - 1);
        cidx = stage_idx[grc];
        cbd  = batch[cidx];
        int g = 0;
        #pragma unroll 1
        while (g + 1 < G && grc >= sCum[g + 1]) g++;
        cgg = g;
    }

    for (int tile = blockIdx.x; tile < ntiles; tile += gridDim.x) {
        const float* px  = x  + (size_t)cidx * 16;
        const float* phn = hn + (size_t)cidx * 64;

        // ---- gather: 5 k-steps, 1x LDG.128 -> fp16 -> STS.64 per step ----
        char* arow = smem + SM_A + grow * RSTRIDE + q * 8;
        #pragma unroll
        for (int j = 0; j < NS1; j++) {
            const int col = 16 * j + 4 * q;
            const float* p = (col < 16) ? (px + col) : (phn + (col - 16));
            const float4 v = *(const float4*)p;
            uint2 h;
            h.x = pack_h2(v.x, v.y);
            h.y = pack_h2(v.z, v.w);
            *(uint2*)(arow + j * SSTRIDE) = h;
        }
        if (q == 0) { sBD[grow] = cbd; sG[grow] = cgg; }

        // prefetch next tile's indices (hidden under MMA phase)
        int nidx, nbd, ngg;
        {
            const int tn  = tile + gridDim.x;
            const int g0  = tn * TILE + grow;
            const int grn = (tn < ntiles) ? ((g0 < M) ? g0 : (M - 1)) : 0;
            nidx = stage_idx[grn];
            nbd  = batch[nidx];
            int g = 0;
            #pragma unroll 1
            while (g + 1 < G && grn >= sCum[g + 1]) g++;
            ngg = g;
        }
        __syncthreads();   // bar 1: A + row-id tables ready

        // ---------------- layer 1: 5 k-steps of m16n8k16 ----------------
        float acc[2][4][4];
        #pragma unroll
        for (int a = 0; a < 2; a++)
            #pragma unroll
            for (int b = 0; b < 4; b++)
                #pragma unroll
                for (int w = 0; w < 4; w++) acc[a][b][w] = 0.f;

        #pragma unroll
        for (int s = 0; s < NS1; s++) {
            uint32_t a[2][4];
            #pragma unroll
            for (int ml = 0; ml < 2; ml++) {
                const char* ap = smem + SM_A + s * SSTRIDE
                                 + (32 * mg + 16 * ml + g4) * RSTRIDE + t4 * 4;
                a[ml][0] = *(const uint32_t*)(ap);
                a[ml][1] = *(const uint32_t*)(ap + 8 * RSTRIDE);
                a[ml][2] = *(const uint32_t*)(ap + 16);
                a[ml][3] = *(const uint32_t*)(ap + 8 * RSTRIDE + 16);
            }
            uint2 bf[4];
            #pragma unroll
            for (int nl = 0; nl < 4; nl++)
                bf[nl] = ((const uint2*)(smem + SM_W1F))[(s * 16 + 4 * ng + nl) * 32 + lane];
            #pragma unroll
            for (int ml = 0; ml < 2; ml++)
                #pragma unroll
                for (int nl = 0; nl < 4; nl++)
                    mma_f16(acc[ml][nl][0], acc[ml][nl][1], acc[ml][nl][2], acc[ml][nl][3],
                            a[ml][0], a[ml][1], a[ml][2], a[ml][3],
                            bf[nl].x, bf[nl].y);
        }

        // ---- epilogue 1: + PD[bd] + PG[g] (fp32, exact), relu, fp16 -> SM_H --
        #pragma unroll
        for (int ml = 0; ml < 2; ml++) {
            const int r0 = 32 * mg + 16 * ml + g4;
            const int bd0 = sBD[r0], bd1 = sBD[r0 + 8];
            const int gg0 = sG[r0],  gg1 = sG[r0 + 8];
            const float* pd0 = g_PD + (size_t)bd0 * 128;
            const float* pd1 = g_PD + (size_t)bd1 * 128;
            const float* pg0 = g_PG + (size_t)gg0 * 128;
            const float* pg1 = g_PG + (size_t)gg1 * 128;
            #pragma unroll
            for (int nl = 0; nl < 4; nl++) {
                const int col0 = 32 * ng + 8 * nl + 2 * t4;
                const float2 d0 = *(const float2*)(pd0 + col0);
                const float2 e0 = *(const float2*)(pg0 + col0);
                const float2 d1 = *(const float2*)(pd1 + col0);
                const float2 e1 = *(const float2*)(pg1 + col0);
                const uint32_t lo = pack_h2(fmaxf(acc[ml][nl][0] + d0.x + e0.x, 0.f),
                                            fmaxf(acc[ml][nl][1] + d0.y + e0.y, 0.f));
                const uint32_t hi = pack_h2(fmaxf(acc[ml][nl][2] + d1.x + e1.x, 0.f),
                                            fmaxf(acc[ml][nl][3] + d1.y + e1.y, 0.f));
                const int s2  = col0 >> 4;
                const int kin = col0 & 15;
                char* hp = smem + SM_H + s2 * SSTRIDE + r0 * RSTRIDE + kin * 2;
                *(uint32_t*)(hp)               = lo;   // row r0
                *(uint32_t*)(hp + 8 * RSTRIDE) = hi;   // row r0+8
            }
        }
        __syncthreads();   // bar 2: H ready

        // ---------------- layer 2: 8 k-steps ----------------
        float ac2[2][2][4];
        #pragma unroll
        for (int a = 0; a < 2; a++)
            #pragma unroll
            for (int b = 0; b < 2; b++)
                #pragma unroll
                for (int w = 0; w < 4; w++) ac2[a][b][w] = 0.f;

        #pragma unroll
        for (int s = 0; s < KS2; s++) {
            uint32_t a[2][4];
            #pragma unroll
            for (int ml = 0; ml < 2; ml++) {
                const char* ap = smem + SM_H + s * SSTRIDE
                                 + (32 * mg + 16 * ml + g4) * RSTRIDE + t4 * 4;
                a[ml][0] = *(const uint32_t*)(ap);
                a[ml][1] = *(const uint32_t*)(ap + 8 * RSTRIDE);
                a[ml][2] = *(const uint32_t*)(ap + 16);
                a[ml][3] = *(const uint32_t*)(ap + 8 * RSTRIDE + 16);
            }
            uint2 bf[2];
            #pragma unroll
            for (int nl = 0; nl < 2; nl++)
                bf[nl] = ((const uint2*)(smem + SM_W2F))[(s * 8 + 2 * ng + nl) * 32 + lane];
            #pragma unroll
            for (int ml = 0; ml < 2; ml++)
                #pragma unroll
                for (int nl = 0; nl < 2; nl++)
                    mma_f16(ac2[ml][nl][0], ac2[ml][nl][1], ac2[ml][nl][2], ac2[ml][nl][3],
                            a[ml][0], a[ml][1], a[ml][2], a[ml][3],
                            bf[nl].x, bf[nl].y);
        }

        // ---- epilogue 2: +b2, relu, dot W3, reduce ----
        #pragma unroll
        for (int ml = 0; ml < 2; ml++) {
            float p0 = 0.f, p1 = 0.f;
            #pragma unroll
            for (int nl = 0; nl < 2; nl++) {
                const int col0 = 16 * ng + 8 * nl + 2 * t4;
                const float2 bb = *(const float2*)(sB2 + col0);
                const float2 ww = *(const float2*)(sW3 + col0);
                p0 += fmaxf(ac2[ml][nl][0] + bb.x, 0.f) * ww.x
                    + fmaxf(ac2[ml][nl][1] + bb.y, 0.f) * ww.y;
                p1 += fmaxf(ac2[ml][nl][2] + bb.x, 0.f) * ww.x
                    + fmaxf(ac2[ml][nl][3] + bb.y, 0.f) * ww.y;
            }
            p0 += __shfl_xor_sync(0xffffffffu, p0, 1);
            p0 += __shfl_xor_sync(0xffffffffu, p0, 2);
            p1 += __shfl_xor_sync(0xffffffffu, p1, 1);
            p1 += __shfl_xor_sync(0xffffffffu, p1, 2);
            if (t4 == 0) {
                const int r0 = 32 * mg + 16 * ml + g4;
                sPt[r0 * 4 + ng]       = p0;
                sPt[(r0 + 8) * 4 + ng] = p1;
            }
        }
        __syncthreads();   // bar 3: partials ready

        if (tid < 128) {
            const float4 p = ((const float4*)sPt)[tid];
            const int go = tile * TILE + tid;
            if (go < M) out[go] = p.x + p.y + p.z + p.w + b3v;
        }

        cidx = nidx; cbd = nbd; cgg = ngg;
    }
}

// ---------------------------------------------------------------------------
extern "C" void kernel_launch(void* const* d_in, const int* in_sizes, int n_in,
                              void* d_out, int out_size) {
    const float* x   = (const float*)d_in[0];
    const float* hn  = (const float*)d_in[1];
    const float* hd  = (const float*)d_in[2];
    const float* hg  = (const float*)d_in[3];
    const float* W1  = (const float*)d_in[4];
    const float* b1  = (const float*)d_in[5];
    const float* W2  = (const float*)d_in[6];
    const float* b2  = (const float*)d_in[7];
    const float* W3  = (const float*)d_in[8];
    const float* b3  = (const float*)d_in[9];
    const int* sidx  = (const int*)d_in[10];
    const int* batch = (const int*)d_in[11];
    const int* nsa   = (const int*)d_in[12];
    float* out = (float*)d_out;

    const int M = in_sizes[10];
    const int G = in_sizes[12];
    int D = in_sizes[2] / 64;
    if (D > 8192) D = 8192;
    int Gc = G; if (Gc > 128) Gc = 128;
    const int ntiles = (M + TILE - 1) / TILE;

    static int sms = 0;
    if (sms == 0) {
        cudaDeviceGetAttribute(&sms, cudaDevAttrMultiProcessorCount, 0);
        cudaFuncSetAttribute(stage_policy_kernel,
                             cudaFuncAttributeMaxDynamicSharedMemorySize, SMEM_TOTAL);
        if (sms <= 0) sms = 148;
    }
    const int grid = (ntiles < sms) ? ntiles : sms;

    precompute_pdg<<<D + Gc, 128>>>(hd, hg, W1, b1, D, Gc);
    stage_policy_kernel<<<grid, 512, SMEM_TOTAL>>>(
        x, hn, W1, W2, b2, W3, b3, sidx, batch, nsa, out, M, G, ntiles);
}